// round 5
// baseline (speedup 1.0000x reference)
#include <cuda_runtime.h>
#include <math.h>
#include <stdint.h>

#define N_LEVELS   16
#define HASH_MASK  0x7FFFFu
#define TABLE_SIZE (1u << 19)
#define N_SMEM_LVL 3            // levels served from shared memory
#define S_MAX      28672        // dense-cell capacity (>= 4096+8000+15625)

struct HashParams {
    int   res[N_LEVELS];
    float resf[N_LEVELS];
    float rcpf[N_LEVELS];   // RN32(1/res), matching XLA's div->mul rewrite
    int   dbase[N_SMEM_LVL + 1];  // dense-grid base offsets; dbase[3] = total
};

__device__ float2 g_dense[S_MAX];

__device__ __forceinline__ unsigned hash_dim(int m, float rcp, unsigned prime)
{
    // corners_f = m * RN32(1/res); q = trunc(RN(cfr+1) * 131072); two roundings.
    float cfr = __fmul_rn((float)m, rcp);
    float t   = __fmul_rn(__fadd_rn(cfr, 1.0f), 131072.0f);
    return (unsigned)t * prime;   // uint32 wrap keeps low 19 bits correct
}

// ---------------------------------------------------------------------------
// Precompute: dense[l][(cx*res+cy)*res+cz] = tables[l][hash(cx,cy,cz)]
// ---------------------------------------------------------------------------
__global__ void build_dense_kernel(const float2* __restrict__ tables, HashParams p)
{
    int id = blockIdx.x * blockDim.x + threadIdx.x;
    if (id >= p.dbase[N_SMEM_LVL]) return;

    int l = 0;
    if (id >= p.dbase[1]) l = 1;
    if (id >= p.dbase[2]) l = 2;
    int cid = id - p.dbase[l];
    int res = p.res[l];
    int cz = cid % res; int t = cid / res;
    int cy = t % res;   int cx = t / res;

    unsigned h = (hash_dim(cx, p.rcpf[l], 1u)
                + hash_dim(cy, p.rcpf[l], 2654435761u)
                + hash_dim(cz, p.rcpf[l], 805459861u)) & HASH_MASK;
    g_dense[id] = tables[(size_t)l * TABLE_SIZE + h];
}

// ---------------------------------------------------------------------------
// Main kernel: levels 0-2 from smem dense grids, levels 3-15 gathered from L2
// ---------------------------------------------------------------------------
__global__ __launch_bounds__(1024, 1)
void hash_encode_kernel(const float* __restrict__ x,
                        const float2* __restrict__ tables,
                        float4* __restrict__ out,
                        int N, HashParams p)
{
    extern __shared__ float2 s_dense[];
    const int dtotal = p.dbase[N_SMEM_LVL];
    for (int i = threadIdx.x; i < dtotal; i += blockDim.x)
        s_dense[i] = g_dense[i];
    __syncthreads();

    int n = blockIdx.x * blockDim.x + threadIdx.x;
    if (n >= N) return;

    float xv0 = fminf(fmaxf(x[n * 3 + 0], -1.0f), 1.0f);
    float xv1 = fminf(fmaxf(x[n * 3 + 1], -1.0f), 1.0f);
    float xv2 = fminf(fmaxf(x[n * 3 + 2], -1.0f), 1.0f);
    float xv[3] = {xv0, xv1, xv2};

    const unsigned PRIME[3] = {1u, 2654435761u, 805459861u};

    float4* o = out + (size_t)n * 8;
    float acc[8];
    int   accw = 0;   // floats buffered in acc
    int   oidx = 0;   // next float4 slot

    // ---- levels 0..2 : shared-memory dense grids --------------------------
#pragma unroll
    for (int l = 0; l < N_SMEM_LVL; l++) {
        const int   resi = p.res[l];
        const float resf = p.resf[l];
        const int   base = p.dbase[l];
        const int   str[3] = {resi * resi, resi, 1};

        int   term[3][2];
        float wgt[3][2];
#pragma unroll
        for (int d = 0; d < 3; d++) {
            float c  = xv[d] * resf;
            float cf = floorf(c);
            float lc = c - cf;
            int   ci = (int)cf;
            wgt[d][0] = 1.0f - lc;
            wgt[d][1] = lc;
#pragma unroll
            for (int b = 0; b < 2; b++) {
                int m = ci + b;
                if (m < 0)     m += resi;
                if (m >= resi) m -= resi;
                term[d][b] = m * str[d];
            }
        }
        float2 f[8];
        float  w[8];
#pragma unroll
        for (int k = 0; k < 8; k++) {
            int b0 = (k >> 2) & 1, b1 = (k >> 1) & 1, b2 = k & 1;
            int idx = term[0][b0] + term[1][b1] + term[2][b2];
            f[k] = s_dense[base + idx];
            w[k] = wgt[0][b0] * wgt[1][b1] * wgt[2][b2];
        }
        float a0 = 0.0f, a1 = 0.0f;
#pragma unroll
        for (int k = 0; k < 8; k++) { a0 += w[k] * f[k].x; a1 += w[k] * f[k].y; }
        acc[accw++] = a0; acc[accw++] = a1;
    }

    // ---- levels 3..15 : hashed gathers (L2-resident tables) ---------------
#pragma unroll
    for (int l = N_SMEM_LVL; l < N_LEVELS; l++) {
        const int   resi = p.res[l];
        const float resf = p.resf[l];
        const float rcp  = p.rcpf[l];
        const float2* __restrict__ tb = tables + (size_t)l * TABLE_SIZE;

        unsigned term[3][2];
        float    wgt[3][2];
#pragma unroll
        for (int d = 0; d < 3; d++) {
            float c  = xv[d] * resf;
            float cf = floorf(c);
            float lc = c - cf;
            int   ci = (int)cf;
            wgt[d][0] = 1.0f - lc;
            wgt[d][1] = lc;
#pragma unroll
            for (int b = 0; b < 2; b++) {
                int m = ci + b;
                if (m < 0)     m += resi;
                if (m >= resi) m -= resi;
                term[d][b] = hash_dim(m, rcp, PRIME[d]);
            }
        }
        float2 f[8];
        float  w[8];
#pragma unroll
        for (int k = 0; k < 8; k++) {
            int b0 = (k >> 2) & 1, b1 = (k >> 1) & 1, b2 = k & 1;
            unsigned h = (term[0][b0] + term[1][b1] + term[2][b2]) & HASH_MASK;
            f[k] = __ldg(tb + h);
            w[k] = wgt[0][b0] * wgt[1][b1] * wgt[2][b2];
        }
        float a0 = 0.0f, a1 = 0.0f;
#pragma unroll
        for (int k = 0; k < 8; k++) { a0 += w[k] * f[k].x; a1 += w[k] * f[k].y; }
        acc[accw++] = a0; acc[accw++] = a1;

        if (accw == 8) {
            o[oidx]     = make_float4(acc[0], acc[1], acc[2], acc[3]);
            o[oidx + 1] = make_float4(acc[4], acc[5], acc[6], acc[7]);
            oidx += 2; accw = 0;
        }
    }
}

extern "C" void kernel_launch(void* const* d_in, const int* in_sizes, int n_in,
                              void* d_out, int out_size)
{
    const float*  x      = (const float*)d_in[0];
    const float2* tables = (const float2*)d_in[1];
    float4*       out    = (float4*)d_out;

    int N = in_sizes[0] / 3;

    HashParams p;
    for (int i = 0; i < N_LEVELS; i++) {
        double r = 16.0 * pow(32.0, (double)i / 15.0);  // same libm as Python ref
        p.res[i]  = (int)r;
        p.resf[i] = (float)p.res[i];
        p.rcpf[i] = 1.0f / p.resf[i];
    }
    int off = 0;
    for (int i = 0; i < N_SMEM_LVL; i++) {
        p.dbase[i] = off;
        off += p.res[i] * p.res[i] * p.res[i];
    }
    p.dbase[N_SMEM_LVL] = off;              // total dense cells (<= S_MAX)

    // Build dense coarse grids (tiny)
    int bt = 256, bb = (off + bt - 1) / bt;
    build_dense_kernel<<<bb, bt>>>(tables, p);

    // Main kernel: 1024 threads, full dynamic smem
    size_t smem = (size_t)off * sizeof(float2);
    cudaFuncSetAttribute(hash_encode_kernel,
                         cudaFuncAttributeMaxDynamicSharedMemorySize, (int)smem);
    int threads = 1024;
    int blocks  = (N + threads - 1) / threads;
    hash_encode_kernel<<<blocks, threads, smem>>>(x, tables, out, N, p);
}

// round 7
// speedup vs baseline: 1.9107x; 1.9107x over previous
#include <cuda_runtime.h>
#include <math.h>
#include <stdint.h>

#define N_LEVELS   16
#define HASH_MASK  0x7FFFFu
#define TABLE_SIZE (1u << 19)
#define NB         32768          // 32^3 sort buckets
#define NMAX       (1 << 20)

struct HashParams {
    int   res[N_LEVELS];
    float resf[N_LEVELS];
    float rcpf[N_LEVELS];   // RN32(1/res), matching XLA's div->mul rewrite
};

__device__ unsigned g_count[NB];
__device__ unsigned g_cursor[NB];
__device__ int      g_perm[NMAX];

// ---------------------------------------------------------------------------
__device__ __forceinline__ int bucket_of(const float* __restrict__ x, int n)
{
    float x0 = fminf(fmaxf(x[n * 3 + 0], -1.0f), 1.0f);
    float x1 = fminf(fmaxf(x[n * 3 + 1], -1.0f), 1.0f);
    float x2 = fminf(fmaxf(x[n * 3 + 2], -1.0f), 1.0f);
    int c0 = min(31, (int)((x0 + 1.0f) * 16.0f));
    int c1 = min(31, (int)((x1 + 1.0f) * 16.0f));
    int c2 = min(31, (int)((x2 + 1.0f) * 16.0f));
    return (c0 << 10) | (c1 << 5) | c2;
}

__global__ void zero_kernel()
{
    int i = blockIdx.x * blockDim.x + threadIdx.x;
    if (i < NB) g_count[i] = 0;
}

__global__ void hist_kernel(const float* __restrict__ x, int N)
{
    int n = blockIdx.x * blockDim.x + threadIdx.x;
    if (n < N) atomicAdd(&g_count[bucket_of(x, n)], 1u);
}

// Single block, 1024 threads: exclusive scan of 32768 bucket counts.
__global__ void scan_kernel()
{
    __shared__ unsigned s[1024];
    int t = threadIdx.x;
    unsigned loc[32], sum = 0;
#pragma unroll
    for (int i = 0; i < 32; i++) { loc[i] = g_count[t * 32 + i]; sum += loc[i]; }
    s[t] = sum;
    __syncthreads();
    for (int d = 1; d < 1024; d <<= 1) {
        unsigned v = (t >= d) ? s[t - d] : 0u;
        __syncthreads();
        s[t] += v;
        __syncthreads();
    }
    unsigned pre = (t == 0) ? 0u : s[t - 1];
#pragma unroll
    for (int i = 0; i < 32; i++) { g_cursor[t * 32 + i] = pre; pre += loc[i]; }
}

__global__ void scatter_kernel(const float* __restrict__ x, int N)
{
    int n = blockIdx.x * blockDim.x + threadIdx.x;
    if (n < N) {
        unsigned pos = atomicAdd(&g_cursor[bucket_of(x, n)], 1u);
        g_perm[pos] = n;
    }
}

// ---------------------------------------------------------------------------
__global__ __launch_bounds__(256, 6)
void hash_encode_kernel(const float* __restrict__ x,
                        const float2* __restrict__ tables,
                        float4* __restrict__ out,
                        int N, int use_perm, HashParams p)
{
    int i = blockIdx.x * blockDim.x + threadIdx.x;
    if (i >= N) return;
    int n = use_perm ? g_perm[i] : i;

    float xv0 = fminf(fmaxf(x[n * 3 + 0], -1.0f), 1.0f);
    float xv1 = fminf(fmaxf(x[n * 3 + 1], -1.0f), 1.0f);
    float xv2 = fminf(fmaxf(x[n * 3 + 2], -1.0f), 1.0f);
    float xv[3] = {xv0, xv1, xv2};

    const unsigned PRIME[3] = {1u, 2654435761u, 805459861u};

    float4* o = out + (size_t)n * 8;

#pragma unroll
    for (int g = 0; g < 4; g++) {
        float accg[8];
#pragma unroll
        for (int li = 0; li < 4; li++) {
            const int   l    = 4 * g + li;
            const int   resi = p.res[l];
            const float resf = p.resf[l];
            const float rcp  = p.rcpf[l];
            const float2* __restrict__ tb = tables + (size_t)l * TABLE_SIZE;

            unsigned term[3][2];
            float    wgt[3][2];
#pragma unroll
            for (int d = 0; d < 3; d++) {
                float c  = xv[d] * resf;
                float cf = floorf(c);
                float lc = c - cf;
                int   ci = (int)cf;
                wgt[d][0] = 1.0f - lc;
                wgt[d][1] = lc;
#pragma unroll
                for (int b = 0; b < 2; b++) {
                    int m = ci + b;
                    if (m < 0)     m += resi;
                    if (m >= resi) m -= resi;
                    // corners_f = m * RN32(1/res)  (XLA div->mul rewrite)
                    float cfr = __fmul_rn((float)m, rcp);
                    // q = trunc(RN(cfr + 1) * 131072), two separate roundings
                    float t = __fmul_rn(__fadd_rn(cfr, 1.0f), 131072.0f);
                    term[d][b] = (unsigned)t * PRIME[d];
                }
            }

            float2 f[8];
            float  w[8];
#pragma unroll
            for (int k = 0; k < 8; k++) {
                int b0 = (k >> 2) & 1, b1 = (k >> 1) & 1, b2 = k & 1;
                unsigned h = (term[0][b0] + term[1][b1] + term[2][b2]) & HASH_MASK;
                f[k] = __ldg(tb + h);
                w[k] = wgt[0][b0] * wgt[1][b1] * wgt[2][b2];
            }
            float a0 = 0.0f, a1 = 0.0f;
#pragma unroll
            for (int k = 0; k < 8; k++) { a0 += w[k] * f[k].x; a1 += w[k] * f[k].y; }
            accg[2 * li]     = a0;
            accg[2 * li + 1] = a1;
        }
        o[2 * g]     = make_float4(accg[0], accg[1], accg[2], accg[3]);
        o[2 * g + 1] = make_float4(accg[4], accg[5], accg[6], accg[7]);
    }
}

extern "C" void kernel_launch(void* const* d_in, const int* in_sizes, int n_in,
                              void* d_out, int out_size)
{
    const float*  x      = (const float*)d_in[0];
    const float2* tables = (const float2*)d_in[1];
    float4*       out    = (float4*)d_out;

    int N = in_sizes[0] / 3;

    HashParams p;
    for (int i = 0; i < N_LEVELS; i++) {
        double r = 16.0 * pow(32.0, (double)i / 15.0);  // same libm as Python ref
        p.res[i]  = (int)r;
        p.resf[i] = (float)p.res[i];
        p.rcpf[i] = 1.0f / p.resf[i];
    }

    int use_perm = (N <= NMAX) ? 1 : 0;
    if (use_perm) {
        zero_kernel<<<(NB + 255) / 256, 256>>>();
        hist_kernel<<<(N + 255) / 256, 256>>>(x, N);
        scan_kernel<<<1, 1024>>>();
        scatter_kernel<<<(N + 255) / 256, 256>>>(x, N);
    }

    int threads = 256;
    int blocks  = (N + threads - 1) / threads;
    hash_encode_kernel<<<blocks, threads>>>(x, tables, out, N, use_perm, p);
}